// round 10
// baseline (speedup 1.0000x reference)
#include <cuda_runtime.h>

// SSKernelDiag: out[h,l] = 2 * Re( sum_n Cc[h,n] * A[h,n]^l )
//   A = exp(abslog + i*phase), dtA = abslog + i*phase, Cc = C*(A-1)/dtA
// H=256, N=64, L=4096, CH=1.
//
// R10: R9's decay truncation + 4-way head split to cut the per-block critical
// path. grid = 1024 (head h, part p); block owns tiles tl = p + 4j, j in
// [0,32); warp w owns j = w + 4k, k in [0,8). Rank-sorted n (desc l_cut) so
// each tile's active set is a rank prefix. Inner: 2 LDS.128 (W) + 4 LDS.64
// (q) + 4 FFMA2 per 4 ranks. 128 threads, 7 blocks/SM target (single wave).

#define HH 256
#define NN 64
#define LL 4096
#define TILE 32
#define BPH 4              // blocks (parts) per head
#define JTILES 32          // tiles per block
#define NTHREADS 128
#define NWARPS 4
#define KPW 8              // tiles per warp
#define CUT 23.0f          // e^-23 ~ 1e-10 magnitude cutoff

typedef unsigned long long ull;

__device__ __forceinline__ float2 cmul(float2 a, float2 b) {
    return make_float2(fmaf(a.x, b.x, -(a.y * b.y)),
                       fmaf(a.x, b.y,  (a.y * b.x)));
}
// exp(i*y), 2-term Cody-Waite reduction; accurate for |y| <~ 2^14.
__device__ __forceinline__ float2 cis_cw(float y) {
    float m = rintf(y * 0.15915494309189535f);
    float r = fmaf(m, -6.28125f, y);
    r = fmaf(m, -1.9353072e-3f, r);
    float s, c;
    __sincosf(r, &s, &c);
    return make_float2(c, s);
}
// A^f = exp(al*f) * cis(ph*f)
__device__ __forceinline__ float2 apow(float al, float ph, float f) {
    float2 cs = cis_cw(ph * f);
    float  e  = __expf(al * f);
    return make_float2(e * cs.x, e * cs.y);
}
__device__ __forceinline__ ull pack2(float x, float y) {
    ull r;
    asm("mov.b64 %0, {%1, %2};" : "=l"(r) : "f"(x), "f"(y));
    return r;
}
__device__ __forceinline__ float2 unpack2(ull v) {
    float x, y;
    asm("mov.b64 {%0, %1}, %2;" : "=f"(x), "=f"(y) : "l"(v));
    return make_float2(x, y);
}
__device__ __forceinline__ void ffma2(ull& acc, ull a, ull b) {
    asm("fma.rn.f32x2 %0, %1, %2, %0;" : "+l"(acc) : "l"(a), "l"(b));
}

__global__ void __launch_bounds__(NTHREADS, 7)
ssk_diag_kernel(const float* __restrict__ abslog,
                const float* __restrict__ phase,
                const float* __restrict__ C,
                float* __restrict__ out) {
    __shared__ float  alR[NN], phR[NN];      // rank-indexed params
    __shared__ float2 CcR[NN];               // rank-indexed 2*Cc
    __shared__ int    lcut[NN];              // by n
    __shared__ int    srt[NN];               // rank -> n
    __shared__ int    cnt4[JTILES];          // active ranks per owned tile
    __shared__ float2 sQr[NN][TILE];         // 16 KB: conj-packed A^t, rank idx
    __shared__ float2 sWbuf[NWARPS][NN];     // 2 KB: per-warp W staging

    const int bid  = blockIdx.x;
    const int h    = bid >> 2;
    const int part = bid & (BPH - 1);
    const int tid  = threadIdx.x;
    const int warp = tid >> 5;
    const int lane = tid & 31;

    const float* alh = abslog + h * NN;
    const float* phh = phase  + h * NN;

    // ---- P1: l_cut per n ----
    if (tid < NN) {
        const float al = alh[tid];
        lcut[tid] = (int)fminf((float)LL, CUT / (-al) + 1.0f);
    }
    __syncthreads();

    // ---- P2: rank (desc l_cut, index tiebreak) + counts for owned tiles ----
    if (tid < NN) {
        const int my = lcut[tid];
        int rank = 0;
        #pragma unroll 8
        for (int m = 0; m < NN; m++) {
            const int o = lcut[m];
            rank += (o > my) || (o == my && m < tid);
        }
        srt[rank] = tid;
    } else if (tid < NN + JTILES) {
        const int j = tid - NN;
        const int lmin = TILE * (part + BPH * j);
        int c = 0;
        #pragma unroll 8
        for (int m = 0; m < NN; m++) c += (lcut[m] > lmin);
        cnt4[j] = (c + 3) & ~3;
    }
    __syncthreads();

    // ---- P3: rank-indexed params + 2*Cc ----
    if (tid < NN) {
        const int n = srt[tid];
        const float al = alh[n];
        const float ph = phh[n];
        alR[tid] = al;
        phR[tid] = ph;
        float er = __expf(al);
        float s0, c0;
        __sincosf(ph, &s0, &c0);
        float2 Am1 = make_float2(er * c0 - 1.0f, er * s0);
        float2 Cin = reinterpret_cast<const float2*>(C)[h * NN + n];
        float2 num = cmul(Cin, Am1);
        float  inv = 1.0f / fmaf(al, al, ph * ph);
        float2 Cc;
        Cc.x = 2.0f * (num.x * al + num.y * ph) * inv;
        Cc.y = 2.0f * (num.y * al - num.x * ph) * inv;
        CcR[tid] = Cc;
    }
    __syncthreads();

    // ---- P4: sQr[r][t] = conj-packed A^t; thread = (r, t-half of 16) ----
    {
        const int r    = tid & 63;
        const int tb   = tid >> 6;               // [0,2)
        const float al = alR[r];
        const float ph = phR[r];
        float2 P  = apow(al, ph, 16.0f * (float)tb);
        float2 A1 = apow(al, ph, 1.0f);
        #pragma unroll
        for (int j = 0; j < 16; j++) {
            sQr[r][16 * tb + j] = make_float2(P.x, -P.y);
            P = cmul(P, A1);
        }
    }

    // ---- P5: per-lane W state (ranks lane, lane+32); step A^512 ----
    float2 W0, W1, S0, S1;
    {
        const float a0 = alR[lane],      p0 = phR[lane];
        const float a1 = alR[lane + 32], p1 = phR[lane + 32];
        const float e0 = (float)(TILE * (part + BPH * warp));  // first tile
        W0 = cmul(CcR[lane],      apow(a0, p0, e0));
        W1 = cmul(CcR[lane + 32], apow(a1, p1, e0));
        S0 = apow(a0, p0, 512.0f);    // tile stride 16 -> exponent 32*16
        S1 = apow(a1, p1, 512.0f);
    }
    __syncthreads();

    // ---- main: 8 tiles per warp ----
    float* outh = out + h * LL;
    const ulonglong2* wb = reinterpret_cast<const ulonglong2*>(sWbuf[warp]);

    #pragma unroll
    for (int k = 0; k < KPW; k++) {
        const int j  = warp + NWARPS * k;
        const int tl = part + BPH * j;
        __syncwarp();
        sWbuf[warp][lane]      = W0;
        sWbuf[warp][lane + 32] = W1;
        __syncwarp();

        const int m = cnt4[j];
        ull acc = pack2(0.0f, 0.0f);
        for (int r = 0; r < m; r += 4) {
            ulonglong2 wa = wb[(r >> 1)];
            ulonglong2 wc = wb[(r >> 1) + 1];
            ull q0 = *reinterpret_cast<const ull*>(&sQr[r + 0][lane]);
            ull q1 = *reinterpret_cast<const ull*>(&sQr[r + 1][lane]);
            ull q2 = *reinterpret_cast<const ull*>(&sQr[r + 2][lane]);
            ull q3 = *reinterpret_cast<const ull*>(&sQr[r + 3][lane]);
            ffma2(acc, wa.x, q0);
            ffma2(acc, wa.y, q1);
            ffma2(acc, wc.x, q2);
            ffma2(acc, wc.y, q3);
        }
        float2 u = unpack2(acc);
        outh[TILE * tl + lane] = u.x + u.y;

        W0 = cmul(W0, S0);
        W1 = cmul(W1, S1);
    }
}

extern "C" void kernel_launch(void* const* d_in, const int* in_sizes, int n_in,
                              void* d_out, int out_size) {
    const float* abslog = (const float*)d_in[0];  // (H, N) f32
    const float* phase  = (const float*)d_in[1];  // (H, N) f32
    const float* C      = (const float*)d_in[2];  // (1, H, N, 2) f32
    float* out = (float*)d_out;                   // (1, H, L) f32

    ssk_diag_kernel<<<HH * BPH, NTHREADS>>>(abslog, phase, C, out);
}